// round 12
// baseline (speedup 1.0000x reference)
#include <cuda_runtime.h>

#define N_SRC   100000
#define N_DST   50000
#define N_EDGES 800000

// Scratch (static device arrays — no allocation)
__device__ int                g_row_ptr[N_DST + 1];
__device__ unsigned int       g_srcb[N_SRC * 32];       // H_src as bf16x2, 12.8MB
__device__ unsigned long long g_wpa[128 * 32];          // (w,w) pairs, outs 4j,4j+1
__device__ unsigned long long g_wpb[128 * 32];          // (w,w) pairs, outs 4j+2,4j+3

__device__ __forceinline__ unsigned long long pack2(float v) {
    unsigned long long r;
    asm("mov.b64 %0, {%1, %1};" : "=l"(r) : "f"(v));
    return r;
}
__device__ __forceinline__ void fma2(unsigned long long& d, unsigned long long a,
                                     unsigned long long b) {
    asm("fma.rn.f32x2 %0, %1, %2, %0;" : "+l"(d) : "l"(a), "l"(b));
}
// pack (lo, hi) floats into bf16x2 (lo in low 16 bits), round-to-nearest
__device__ __forceinline__ unsigned int bf2(float lo, float hi) {
    unsigned int r;
    asm("cvt.rn.bf16x2.f32 %0, %1, %2;" : "=r"(r) : "f"(hi), "f"(lo));
    return r;
}

// ---------------------------------------------------------------------------
// Prep (merged, 3 block populations):
//  [0, QUAD_BLOCKS):            row_ptr from sorted dst_idx (4 edges/thread)
//  [QUAD_BLOCKS, +W_BLOCKS):    W [64][128] -> pre-packed pair arrays
//  [.., +CVT_BLOCKS):           H_src fp32 -> bf16x2 (streaming)
// ---------------------------------------------------------------------------
#define N_QUADS     (N_EDGES / 4)
#define QUAD_BLOCKS ((N_QUADS + 255) / 256)            // 782
#define W_BLOCKS    ((64 * 128 + 255) / 256)           // 32
#define N_CVT       (N_SRC * 64 / 4)                   // 1.6M float4 units
#define CVT_BLOCKS  ((N_CVT + 255) / 256)              // 6250

__global__ void prep_kernel(const int* __restrict__ dst_idx,
                            const float* __restrict__ W,
                            const float* __restrict__ H_src) {
    if (blockIdx.x >= QUAD_BLOCKS + W_BLOCKS) {
        // ---- H_src -> bf16 convert: thread i handles one float4 ----
        int i = (blockIdx.x - QUAD_BLOCKS - W_BLOCKS) * blockDim.x + threadIdx.x;
        if (i < N_CVT) {
            float4 v = ((const float4*)H_src)[i];
            uint2 p;
            p.x = bf2(v.x, v.y);
            p.y = bf2(v.z, v.w);
            ((uint2*)g_srcb)[i] = p;
        }
        return;
    }
    if (blockIdx.x >= QUAD_BLOCKS) {
        // ---- W transpose + pair-pack ----
        int t = (blockIdx.x - QUAD_BLOCKS) * blockDim.x + threadIdx.x;
        if (t < 64 * 128) {
            int o = t >> 7;          // 0..63
            int k = t & 127;         // 0..127
            unsigned long long pv = pack2(W[o * 128 + k]);
            int slot = k * 32 + (o >> 2) * 2 + (o & 1);
            if ((o & 3) < 2) g_wpa[slot] = pv;
            else             g_wpb[k * 32 + (o >> 2) * 2 + ((o & 3) - 2)] = pv;
        }
        return;
    }
    // ---- row_ptr build, 4 edges per thread ----
    int q = blockIdx.x * blockDim.x + threadIdx.x;
    if (q >= N_QUADS) return;
    int e0 = q * 4;
    int4 d4 = ((const int4*)dst_idx)[q];
    int dprev = (e0 == 0) ? -1 : __ldg(&dst_idx[e0 - 1]);
    for (int x = dprev + 1; x <= d4.x; ++x) g_row_ptr[x] = e0;
    for (int x = d4.x + 1; x <= d4.y; ++x) g_row_ptr[x] = e0 + 1;
    for (int x = d4.y + 1; x <= d4.z; ++x) g_row_ptr[x] = e0 + 2;
    for (int x = d4.z + 1; x <= d4.w; ++x) g_row_ptr[x] = e0 + 3;
    if (e0 + 4 == N_EDGES) {
        for (int x = d4.w + 1; x <= N_DST; ++x) g_row_ptr[x] = N_EDGES;
    }
}

// ---------------------------------------------------------------------------
// Kernel B: aggregation (bf16 gather) + CV blend. Warp per dst row.
// Gather bytes halved vs fp32: 128B/edge/warp. bf16->fp32 = 16-bit shift.
// ---------------------------------------------------------------------------
#define AGG_THREADS 256
#define AGG_ROWS    8

__global__ __launch_bounds__(AGG_THREADS) void aggregate_kernel(
    const float* __restrict__ HBar,
    const int*   __restrict__ src_idx,
    float* __restrict__ out_hn)
{
    const int warp = threadIdx.x >> 5;
    const int lane = threadIdx.x & 31;
    const int row  = blockIdx.x * AGG_ROWS + warp;
    if (row >= N_DST) return;

    const int start = g_row_ptr[row];
    const int end   = g_row_ptr[row + 1];
    const int deg   = end - start;

    float2 hb = ((const float2*)HBar)[row * 32 + lane];

    float sx = 0.f, sy = 0.f;
    int e = start;
    for (; e + 7 < end; e += 8) {
        int s0 = src_idx[e + 0], s1 = src_idx[e + 1];
        int s2 = src_idx[e + 2], s3 = src_idx[e + 3];
        int s4 = src_idx[e + 4], s5 = src_idx[e + 5];
        int s6 = src_idx[e + 6], s7 = src_idx[e + 7];
        unsigned int u0 = __ldg(&g_srcb[s0 * 32 + lane]);
        unsigned int u1 = __ldg(&g_srcb[s1 * 32 + lane]);
        unsigned int u2 = __ldg(&g_srcb[s2 * 32 + lane]);
        unsigned int u3 = __ldg(&g_srcb[s3 * 32 + lane]);
        unsigned int u4 = __ldg(&g_srcb[s4 * 32 + lane]);
        unsigned int u5 = __ldg(&g_srcb[s5 * 32 + lane]);
        unsigned int u6 = __ldg(&g_srcb[s6 * 32 + lane]);
        unsigned int u7 = __ldg(&g_srcb[s7 * 32 + lane]);
        sx += __uint_as_float(u0 << 16) + __uint_as_float(u1 << 16)
            + __uint_as_float(u2 << 16) + __uint_as_float(u3 << 16)
            + __uint_as_float(u4 << 16) + __uint_as_float(u5 << 16)
            + __uint_as_float(u6 << 16) + __uint_as_float(u7 << 16);
        sy += __uint_as_float(u0 & 0xffff0000u) + __uint_as_float(u1 & 0xffff0000u)
            + __uint_as_float(u2 & 0xffff0000u) + __uint_as_float(u3 & 0xffff0000u)
            + __uint_as_float(u4 & 0xffff0000u) + __uint_as_float(u5 & 0xffff0000u)
            + __uint_as_float(u6 & 0xffff0000u) + __uint_as_float(u7 & 0xffff0000u);
    }
    for (; e < end; ++e) {
        int s = src_idx[e];
        unsigned int u = __ldg(&g_srcb[s * 32 + lane]);
        sx += __uint_as_float(u << 16);
        sy += __uint_as_float(u & 0xffff0000u);
    }

    float inv = 1.0f / (float)max(deg, 1);
    float2 hn;
    hn.x = 0.9f * hb.x + 0.1f * (sx * inv);
    hn.y = 0.9f * hb.y + 0.1f * (sy * inv);
    ((float2*)out_hn)[row * 32 + lane] = hn;
}

// ---------------------------------------------------------------------------
// Kernel C: GEMM  h = relu([H_dst | h_neigh] @ W^T + b)
// 64 rows x 64 outs per 128-thread block, K=128, 8 rows x 4 outs per thread.
// Per k: 2 LDS.128 + 2 LDG.128 (pre-packed W pairs, contiguous 256B/warp)
// + 16 fma.rn.f32x2  => 20 inst / 32 FMA. 7 blocks/SM (224KB smem).
// ---------------------------------------------------------------------------
#define G_ROWS    64
#define G_THREADS 128
#define GEMM_BLOCKS ((N_DST + G_ROWS - 1) / G_ROWS)   // 782

__global__ __launch_bounds__(G_THREADS, 7) void gemm_kernel(
    const float* __restrict__ H_dst,
    const float* __restrict__ hn,
    const float* __restrict__ bias,
    float* __restrict__ out_h)
{
    __shared__ float xt[128][64];   // 32KB, k-major, swizzle r ^ (k & 56)

    const int tid = threadIdx.x;
    const int rowBase = blockIdx.x * G_ROWS;

    for (int i = tid; i < 64 * 16; i += G_THREADS) {
        int r  = i >> 4;
        int c4 = i & 15;
        int row = rowBase + r;
        float4 vd = make_float4(0.f, 0.f, 0.f, 0.f);
        float4 vn = make_float4(0.f, 0.f, 0.f, 0.f);
        if (row < N_DST) {
            vd = ((const float4*)H_dst)[row * 16 + c4];
            vn = ((const float4*)hn)   [row * 16 + c4];
        }
        int k0 = 4 * c4;
        xt[k0 + 0][r ^ ((k0 + 0) & 56)] = vd.x;
        xt[k0 + 1][r ^ ((k0 + 1) & 56)] = vd.y;
        xt[k0 + 2][r ^ ((k0 + 2) & 56)] = vd.z;
        xt[k0 + 3][r ^ ((k0 + 3) & 56)] = vd.w;
        int k1 = 64 + 4 * c4;
        xt[k1 + 0][r ^ ((k1 + 0) & 56)] = vn.x;
        xt[k1 + 1][r ^ ((k1 + 1) & 56)] = vn.y;
        xt[k1 + 2][r ^ ((k1 + 2) & 56)] = vn.z;
        xt[k1 + 3][r ^ ((k1 + 3) & 56)] = vn.w;
    }
    __syncthreads();

    const int rg = tid >> 4;    // 0..7  -> rows 8*rg .. 8*rg+7
    const int cg = tid & 15;    // 0..15 -> outs 4*cg .. 4*cg+3

    unsigned long long acc[4][4];
#pragma unroll
    for (int p = 0; p < 4; p++)
#pragma unroll
        for (int j = 0; j < 4; j++) acc[p][j] = 0ULL;

    const ulonglong2* wpa = (const ulonglong2*)g_wpa;
    const ulonglong2* wpb = (const ulonglong2*)g_wpb;

#pragma unroll 8
    for (int k = 0; k < 128; k++) {
        const int sw = k & 56;
        const int base = (8 * rg) ^ sw;           // 8-aligned
        ulonglong2 xlo = *(const ulonglong2*)&xt[k][base];      // rows 8rg..+3
        ulonglong2 xhi = *(const ulonglong2*)&xt[k][base + 4];  // rows 8rg+4..+7

        ulonglong2 wa = __ldg(&wpa[k * 16 + cg]);  // packs for outs 4cg, 4cg+1
        ulonglong2 wb = __ldg(&wpb[k * 16 + cg]);  // packs for outs 4cg+2, 4cg+3

        fma2(acc[0][0], xlo.x, wa.x); fma2(acc[0][1], xlo.x, wa.y);
        fma2(acc[0][2], xlo.x, wb.x); fma2(acc[0][3], xlo.x, wb.y);
        fma2(acc[1][0], xlo.y, wa.x); fma2(acc[1][1], xlo.y, wa.y);
        fma2(acc[1][2], xlo.y, wb.x); fma2(acc[1][3], xlo.y, wb.y);
        fma2(acc[2][0], xhi.x, wa.x); fma2(acc[2][1], xhi.x, wa.y);
        fma2(acc[2][2], xhi.x, wb.x); fma2(acc[2][3], xhi.x, wb.y);
        fma2(acc[3][0], xhi.y, wa.x); fma2(acc[3][1], xhi.y, wa.y);
        fma2(acc[3][2], xhi.y, wb.x); fma2(acc[3][3], xhi.y, wb.y);
    }

    float4 bv = __ldg(&((const float4*)bias)[cg]);
#pragma unroll
    for (int p = 0; p < 4; p++) {
        float lo[4], hi[4];
#pragma unroll
        for (int j = 0; j < 4; j++) {
            float l, h;
            asm("mov.b64 {%0, %1}, %2;" : "=f"(l), "=f"(h) : "l"(acc[p][j]));
            lo[j] = l; hi[j] = h;
        }
        int r0 = rowBase + 8 * rg + 2 * p;
        if (r0 < N_DST) {
            float4 v;
            v.x = fmaxf(lo[0] + bv.x, 0.f);
            v.y = fmaxf(lo[1] + bv.y, 0.f);
            v.z = fmaxf(lo[2] + bv.z, 0.f);
            v.w = fmaxf(lo[3] + bv.w, 0.f);
            ((float4*)out_h)[r0 * 16 + cg] = v;
        }
        if (r0 + 1 < N_DST) {
            float4 v;
            v.x = fmaxf(hi[0] + bv.x, 0.f);
            v.y = fmaxf(hi[1] + bv.y, 0.f);
            v.z = fmaxf(hi[2] + bv.z, 0.f);
            v.w = fmaxf(hi[3] + bv.w, 0.f);
            ((float4*)out_h)[(r0 + 1) * 16 + cg] = v;
        }
    }
}

// ---------------------------------------------------------------------------
extern "C" void kernel_launch(void* const* d_in, const int* in_sizes, int n_in,
                              void* d_out, int out_size) {
    const float* H_src   = (const float*)d_in[0];
    const float* H_dst   = (const float*)d_in[1];
    const float* HBar    = (const float*)d_in[2];
    const int*   src_idx = (const int*)  d_in[3];
    const int*   dst_idx = (const int*)  d_in[4];
    const float* W       = (const float*)d_in[5];
    const float* bias    = (const float*)d_in[6];

    float* out_h  = (float*)d_out;                     // [N_DST, 64]
    float* out_hn = (float*)d_out + N_DST * 64;        // [N_DST, 64]

    prep_kernel<<<QUAD_BLOCKS + W_BLOCKS + CVT_BLOCKS, 256>>>(dst_idx, W, H_src);

    aggregate_kernel<<<(N_DST + AGG_ROWS - 1) / AGG_ROWS, AGG_THREADS>>>(
        HBar, src_idx, out_hn);

    gemm_kernel<<<GEMM_BLOCKS, G_THREADS>>>(H_dst, out_hn, bias, out_h);
}

// round 13
// speedup vs baseline: 1.0081x; 1.0081x over previous
#include <cuda_runtime.h>

#define N_SRC   100000
#define N_DST   50000
#define N_EDGES 800000

// Scratch (static device arrays — no allocation)
__device__ int                g_row_ptr[N_DST + 1];
__device__ unsigned long long g_wpa[128 * 32];   // (w,w) pairs, outs 4j,4j+1, k-major
__device__ unsigned long long g_wpb[128 * 32];   // (w,w) pairs, outs 4j+2,4j+3

__device__ __forceinline__ unsigned long long pack2(float v) {
    unsigned long long r;
    asm("mov.b64 %0, {%1, %1};" : "=l"(r) : "f"(v));
    return r;
}
__device__ __forceinline__ void fma2(unsigned long long& d, unsigned long long a,
                                     unsigned long long b) {
    asm("fma.rn.f32x2 %0, %1, %2, %0;" : "+l"(d) : "l"(a), "l"(b));
}

// ---------------------------------------------------------------------------
// Prep (merged):
//  [0, QUAD_BLOCKS):         row_ptr from sorted dst_idx (4 edges/thread, int4)
//  [QUAD_BLOCKS, +W_BLOCKS): W [64][128] -> pre-packed (w,w) pair arrays
// ---------------------------------------------------------------------------
#define N_QUADS     (N_EDGES / 4)
#define QUAD_BLOCKS ((N_QUADS + 255) / 256)            // 782
#define W_BLOCKS    ((64 * 128 + 255) / 256)           // 32

__global__ void prep_kernel(const int* __restrict__ dst_idx,
                            const float* __restrict__ W) {
    if (blockIdx.x >= QUAD_BLOCKS) {
        int t = (blockIdx.x - QUAD_BLOCKS) * blockDim.x + threadIdx.x;
        if (t < 64 * 128) {
            int o = t >> 7;          // 0..63
            int k = t & 127;         // 0..127
            unsigned long long pv = pack2(W[o * 128 + k]);
            if ((o & 3) < 2) g_wpa[k * 32 + (o >> 2) * 2 + (o & 1)] = pv;
            else             g_wpb[k * 32 + (o >> 2) * 2 + ((o & 3) - 2)] = pv;
        }
        return;
    }
    int q = blockIdx.x * blockDim.x + threadIdx.x;
    if (q >= N_QUADS) return;
    int e0 = q * 4;
    int4 d4 = ((const int4*)dst_idx)[q];
    int dprev = (e0 == 0) ? -1 : __ldg(&dst_idx[e0 - 1]);
    for (int x = dprev + 1; x <= d4.x; ++x) g_row_ptr[x] = e0;
    for (int x = d4.x + 1; x <= d4.y; ++x) g_row_ptr[x] = e0 + 1;
    for (int x = d4.y + 1; x <= d4.z; ++x) g_row_ptr[x] = e0 + 2;
    for (int x = d4.z + 1; x <= d4.w; ++x) g_row_ptr[x] = e0 + 3;
    if (e0 + 4 == N_EDGES) {
        for (int x = d4.w + 1; x <= N_DST; ++x) g_row_ptr[x] = N_EDGES;
    }
}

// ---------------------------------------------------------------------------
// Kernel B: aggregation + CV blend (fp32, measured near L2 gather floor).
// Warp per dst row, 8-way unrolled gather, no smem.
// ---------------------------------------------------------------------------
#define AGG_THREADS 256
#define AGG_ROWS    8

__global__ __launch_bounds__(AGG_THREADS) void aggregate_kernel(
    const float* __restrict__ H_src,
    const float* __restrict__ HBar,
    const int*   __restrict__ src_idx,
    float* __restrict__ out_hn)
{
    const int warp = threadIdx.x >> 5;
    const int lane = threadIdx.x & 31;
    const int row  = blockIdx.x * AGG_ROWS + warp;
    if (row >= N_DST) return;

    const int start = g_row_ptr[row];
    const int end   = g_row_ptr[row + 1];
    const int deg   = end - start;

    const float2* Hs2 = (const float2*)H_src;
    float2 hb = ((const float2*)HBar)[row * 32 + lane];

    float2 sum = make_float2(0.f, 0.f);
    int e = start;
    for (; e + 7 < end; e += 8) {
        int s0 = src_idx[e + 0], s1 = src_idx[e + 1];
        int s2 = src_idx[e + 2], s3 = src_idx[e + 3];
        int s4 = src_idx[e + 4], s5 = src_idx[e + 5];
        int s6 = src_idx[e + 6], s7 = src_idx[e + 7];
        float2 a0 = Hs2[s0 * 32 + lane];
        float2 a1 = Hs2[s1 * 32 + lane];
        float2 a2 = Hs2[s2 * 32 + lane];
        float2 a3 = Hs2[s3 * 32 + lane];
        float2 a4 = Hs2[s4 * 32 + lane];
        float2 a5 = Hs2[s5 * 32 + lane];
        float2 a6 = Hs2[s6 * 32 + lane];
        float2 a7 = Hs2[s7 * 32 + lane];
        sum.x += ((a0.x + a1.x) + (a2.x + a3.x)) + ((a4.x + a5.x) + (a6.x + a7.x));
        sum.y += ((a0.y + a1.y) + (a2.y + a3.y)) + ((a4.y + a5.y) + (a6.y + a7.y));
    }
    for (; e + 1 < end; e += 2) {
        int s0 = src_idx[e + 0], s1 = src_idx[e + 1];
        float2 a0 = Hs2[s0 * 32 + lane];
        float2 a1 = Hs2[s1 * 32 + lane];
        sum.x += a0.x + a1.x;
        sum.y += a0.y + a1.y;
    }
    if (e < end) {
        int s = src_idx[e];
        float2 a = Hs2[s * 32 + lane];
        sum.x += a.x;
        sum.y += a.y;
    }

    float inv = 1.0f / (float)max(deg, 1);
    float2 hn;
    hn.x = 0.9f * hb.x + 0.1f * (sum.x * inv);
    hn.y = 0.9f * hb.y + 0.1f * (sum.y * inv);
    ((float2*)out_hn)[row * 32 + lane] = hn;
}

// ---------------------------------------------------------------------------
// Kernel C: GEMM  h = relu([H_dst | h_neigh] @ W^T + b)
// 64 rows x 64 outs per 128-thread block, K=128, 8 rows x 4 outs per thread.
// Per k: 2 LDS.128 + 2 LDG.128 (pre-packed W pairs, contiguous 256B/warp)
// + 16 fma.rn.f32x2 => 20 inst / 32 FMA, no packs (LDG feeds FMA directly).
// X k-major in 32KB smem, swizzle r ^ (k & 56). 7 blocks/SM.
// ---------------------------------------------------------------------------
#define G_ROWS    64
#define G_THREADS 128
#define GEMM_BLOCKS ((N_DST + G_ROWS - 1) / G_ROWS)   // 782

__global__ __launch_bounds__(G_THREADS, 7) void gemm_kernel(
    const float* __restrict__ H_dst,
    const float* __restrict__ hn,
    const float* __restrict__ bias,
    float* __restrict__ out_h)
{
    __shared__ float xt[128][64];   // 32KB

    const int tid = threadIdx.x;
    const int rowBase = blockIdx.x * G_ROWS;

    for (int i = tid; i < 64 * 16; i += G_THREADS) {
        int r  = i >> 4;
        int c4 = i & 15;
        int row = rowBase + r;
        float4 vd = make_float4(0.f, 0.f, 0.f, 0.f);
        float4 vn = make_float4(0.f, 0.f, 0.f, 0.f);
        if (row < N_DST) {
            vd = ((const float4*)H_dst)[row * 16 + c4];
            vn = ((const float4*)hn)   [row * 16 + c4];
        }
        int k0 = 4 * c4;
        xt[k0 + 0][r ^ ((k0 + 0) & 56)] = vd.x;
        xt[k0 + 1][r ^ ((k0 + 1) & 56)] = vd.y;
        xt[k0 + 2][r ^ ((k0 + 2) & 56)] = vd.z;
        xt[k0 + 3][r ^ ((k0 + 3) & 56)] = vd.w;
        int k1 = 64 + 4 * c4;
        xt[k1 + 0][r ^ ((k1 + 0) & 56)] = vn.x;
        xt[k1 + 1][r ^ ((k1 + 1) & 56)] = vn.y;
        xt[k1 + 2][r ^ ((k1 + 2) & 56)] = vn.z;
        xt[k1 + 3][r ^ ((k1 + 3) & 56)] = vn.w;
    }
    __syncthreads();

    const int rg = tid >> 4;    // 0..7  -> rows 8*rg .. 8*rg+7
    const int cg = tid & 15;    // 0..15 -> outs 4*cg .. 4*cg+3

    unsigned long long acc[4][4];
#pragma unroll
    for (int p = 0; p < 4; p++)
#pragma unroll
        for (int j = 0; j < 4; j++) acc[p][j] = 0ULL;

    const ulonglong2* wpa = (const ulonglong2*)g_wpa;
    const ulonglong2* wpb = (const ulonglong2*)g_wpb;

#pragma unroll 8
    for (int k = 0; k < 128; k++) {
        const int sw = k & 56;
        const int base = (8 * rg) ^ sw;           // 8-aligned
        ulonglong2 xlo = *(const ulonglong2*)&xt[k][base];      // rows 8rg..+3
        ulonglong2 xhi = *(const ulonglong2*)&xt[k][base + 4];  // rows 8rg+4..+7

        ulonglong2 wa = __ldg(&wpa[k * 16 + cg]);  // packs for outs 4cg, 4cg+1
        ulonglong2 wb = __ldg(&wpb[k * 16 + cg]);  // packs for outs 4cg+2, 4cg+3

        fma2(acc[0][0], xlo.x, wa.x); fma2(acc[0][1], xlo.x, wa.y);
        fma2(acc[0][2], xlo.x, wb.x); fma2(acc[0][3], xlo.x, wb.y);
        fma2(acc[1][0], xlo.y, wa.x); fma2(acc[1][1], xlo.y, wa.y);
        fma2(acc[1][2], xlo.y, wb.x); fma2(acc[1][3], xlo.y, wb.y);
        fma2(acc[2][0], xhi.x, wa.x); fma2(acc[2][1], xhi.x, wa.y);
        fma2(acc[2][2], xhi.x, wb.x); fma2(acc[2][3], xhi.x, wb.y);
        fma2(acc[3][0], xhi.y, wa.x); fma2(acc[3][1], xhi.y, wa.y);
        fma2(acc[3][2], xhi.y, wb.x); fma2(acc[3][3], xhi.y, wb.y);
    }

    float4 bv = __ldg(&((const float4*)bias)[cg]);
#pragma unroll
    for (int p = 0; p < 4; p++) {
        float lo[4], hi[4];
#pragma unroll
        for (int j = 0; j < 4; j++) {
            float l, h;
            asm("mov.b64 {%0, %1}, %2;" : "=f"(l), "=f"(h) : "l"(acc[p][j]));
            lo[j] = l; hi[j] = h;
        }
        int r0 = rowBase + 8 * rg + 2 * p;
        if (r0 < N_DST) {
            float4 v;
            v.x = fmaxf(lo[0] + bv.x, 0.f);
            v.y = fmaxf(lo[1] + bv.y, 0.f);
            v.z = fmaxf(lo[2] + bv.z, 0.f);
            v.w = fmaxf(lo[3] + bv.w, 0.f);
            ((float4*)out_h)[r0 * 16 + cg] = v;
        }
        if (r0 + 1 < N_DST) {
            float4 v;
            v.x = fmaxf(hi[0] + bv.x, 0.f);
            v.y = fmaxf(hi[1] + bv.y, 0.f);
            v.z = fmaxf(hi[2] + bv.z, 0.f);
            v.w = fmaxf(hi[3] + bv.w, 0.f);
            ((float4*)out_h)[(r0 + 1) * 16 + cg] = v;
        }
    }
}

// ---------------------------------------------------------------------------
extern "C" void kernel_launch(void* const* d_in, const int* in_sizes, int n_in,
                              void* d_out, int out_size) {
    const float* H_src   = (const float*)d_in[0];
    const float* H_dst   = (const float*)d_in[1];
    const float* HBar    = (const float*)d_in[2];
    const int*   src_idx = (const int*)  d_in[3];
    const int*   dst_idx = (const int*)  d_in[4];
    const float* W       = (const float*)d_in[5];
    const float* bias    = (const float*)d_in[6];

    float* out_h  = (float*)d_out;                     // [N_DST, 64]
    float* out_hn = (float*)d_out + N_DST * 64;        // [N_DST, 64]

    prep_kernel<<<QUAD_BLOCKS + W_BLOCKS, 256>>>(dst_idx, W);

    aggregate_kernel<<<(N_DST + AGG_ROWS - 1) / AGG_ROWS, AGG_THREADS>>>(
        H_src, HBar, src_idx, out_hn);

    gemm_kernel<<<GEMM_BLOCKS, G_THREADS>>>(H_dst, out_hn, bias, out_h);
}

// round 16
// speedup vs baseline: 1.2997x; 1.2893x over previous
#include <cuda_runtime.h>
#include <cuda_bf16.h>
#include <cstdint>

#define N_SRC   100000
#define N_DST   50000
#define N_EDGES 800000

// Scratch (static device arrays — no allocation)
__device__ int g_row_ptr[N_DST + 1];
// W hi/lo bf16, padded-row layout identical to the GEMM's smem tiles:
// row n (0..63), byte offset n*272 + k*2  (272 = 17*16B padded row stride)
#define XPAD 272
__device__ __align__(16) char g_wbhi[64 * XPAD];
__device__ __align__(16) char g_wblo[64 * XPAD];

__device__ __forceinline__ uint32_t smem_to_u32(const void* p) {
    uint32_t a;
    asm("{ .reg .u64 t; cvta.to.shared.u64 t, %1; cvt.u32.u64 %0, t; }"
        : "=r"(a) : "l"(p));
    return a;
}
// pack (lo, hi) floats into bf16x2 (lo in low 16 bits), round-to-nearest
__device__ __forceinline__ uint32_t bf2(float lo, float hi) {
    uint32_t r;
    asm("cvt.rn.bf16x2.f32 %0, %1, %2;" : "=r"(r) : "f"(hi), "f"(lo));
    return r;
}
__device__ __forceinline__ float bflo_f(uint32_t u) { return __uint_as_float(u << 16); }
__device__ __forceinline__ float bfhi_f(uint32_t u) { return __uint_as_float(u & 0xffff0000u); }

__device__ __forceinline__ void ldsm_x4(uint32_t* r, uint32_t addr) {
    asm volatile("ldmatrix.sync.aligned.m8n8.x4.shared.b16 {%0,%1,%2,%3}, [%4];"
                 : "=r"(r[0]), "=r"(r[1]), "=r"(r[2]), "=r"(r[3]) : "r"(addr));
}
__device__ __forceinline__ void mma_bf16(float* d, const uint32_t* a,
                                         uint32_t b0, uint32_t b1) {
    asm volatile(
        "mma.sync.aligned.m16n8k16.row.col.f32.bf16.bf16.f32 "
        "{%0,%1,%2,%3}, {%4,%5,%6,%7}, {%8,%9}, {%0,%1,%2,%3};"
        : "+f"(d[0]), "+f"(d[1]), "+f"(d[2]), "+f"(d[3])
        : "r"(a[0]), "r"(a[1]), "r"(a[2]), "r"(a[3]), "r"(b0), "r"(b1));
}

// ===========================================================================
// Prep: row_ptr from sorted dst_idx (4 edges/thread, int4) + W -> split-bf16
// padded-row images (ready for linear smem copy in the GEMM kernel).
// ===========================================================================
#define N_QUADS     (N_EDGES / 4)
#define QUAD_BLOCKS ((N_QUADS + 255) / 256)            // 782
#define W_BLOCKS    ((64 * 128 + 255) / 256)           // 32

__global__ void prep_kernel(const int* __restrict__ dst_idx,
                            const float* __restrict__ W) {
    if (blockIdx.x >= QUAD_BLOCKS) {
        int t = (blockIdx.x - QUAD_BLOCKS) * blockDim.x + threadIdx.x;
        if (t < 64 * 128) {
            int n = t >> 7;          // 0..63  (output / W row)
            int k = t & 127;         // 0..127
            float w = W[n * 128 + k];
            __nv_bfloat16 whi = __float2bfloat16(w);
            __nv_bfloat16 wlo = __float2bfloat16(w - __bfloat162float(whi));
            *(__nv_bfloat16*)&g_wbhi[n * XPAD + k * 2] = whi;
            *(__nv_bfloat16*)&g_wblo[n * XPAD + k * 2] = wlo;
        }
        return;
    }
    int q = blockIdx.x * blockDim.x + threadIdx.x;
    if (q >= N_QUADS) return;
    int e0 = q * 4;
    int4 d4 = ((const int4*)dst_idx)[q];
    int dprev = (e0 == 0) ? -1 : __ldg(&dst_idx[e0 - 1]);
    for (int x = dprev + 1; x <= d4.x; ++x) g_row_ptr[x] = e0;
    for (int x = d4.x + 1; x <= d4.y; ++x) g_row_ptr[x] = e0 + 1;
    for (int x = d4.y + 1; x <= d4.z; ++x) g_row_ptr[x] = e0 + 2;
    for (int x = d4.z + 1; x <= d4.w; ++x) g_row_ptr[x] = e0 + 3;
    if (e0 + 4 == N_EDGES) {
        for (int x = d4.w + 1; x <= N_DST; ++x) g_row_ptr[x] = N_EDGES;
    }
}

// ===========================================================================
// Aggregation + CV blend (fp32, measured near the L2 gather floor).
// ===========================================================================
#define AGG_THREADS 256
#define AGG_ROWS    8

__global__ __launch_bounds__(AGG_THREADS) void aggregate_kernel(
    const float* __restrict__ H_src,
    const float* __restrict__ HBar,
    const int*   __restrict__ src_idx,
    float* __restrict__ out_hn)
{
    const int warp = threadIdx.x >> 5;
    const int lane = threadIdx.x & 31;
    const int row  = blockIdx.x * AGG_ROWS + warp;
    if (row >= N_DST) return;

    const int start = g_row_ptr[row];
    const int end   = g_row_ptr[row + 1];
    const int deg   = end - start;

    const float2* Hs2 = (const float2*)H_src;
    float2 hb = ((const float2*)HBar)[row * 32 + lane];

    float2 sum = make_float2(0.f, 0.f);
    int e = start;
    for (; e + 7 < end; e += 8) {
        int s0 = src_idx[e + 0], s1 = src_idx[e + 1];
        int s2 = src_idx[e + 2], s3 = src_idx[e + 3];
        int s4 = src_idx[e + 4], s5 = src_idx[e + 5];
        int s6 = src_idx[e + 6], s7 = src_idx[e + 7];
        float2 a0 = Hs2[s0 * 32 + lane];
        float2 a1 = Hs2[s1 * 32 + lane];
        float2 a2 = Hs2[s2 * 32 + lane];
        float2 a3 = Hs2[s3 * 32 + lane];
        float2 a4 = Hs2[s4 * 32 + lane];
        float2 a5 = Hs2[s5 * 32 + lane];
        float2 a6 = Hs2[s6 * 32 + lane];
        float2 a7 = Hs2[s7 * 32 + lane];
        sum.x += ((a0.x + a1.x) + (a2.x + a3.x)) + ((a4.x + a5.x) + (a6.x + a7.x));
        sum.y += ((a0.y + a1.y) + (a2.y + a3.y)) + ((a4.y + a5.y) + (a6.y + a7.y));
    }
    for (; e + 1 < end; e += 2) {
        int s0 = src_idx[e + 0], s1 = src_idx[e + 1];
        float2 a0 = Hs2[s0 * 32 + lane];
        float2 a1 = Hs2[s1 * 32 + lane];
        sum.x += a0.x + a1.x;
        sum.y += a0.y + a1.y;
    }
    if (e < end) {
        int s = src_idx[e];
        float2 a = Hs2[s * 32 + lane];
        sum.x += a.x;
        sum.y += a.y;
    }

    float inv = 1.0f / (float)max(deg, 1);
    float2 hn;
    hn.x = 0.9f * hb.x + 0.1f * (sum.x * inv);
    hn.y = 0.9f * hb.y + 0.1f * (sum.y * inv);
    ((float2*)out_hn)[row * 32 + lane] = hn;
}

// ===========================================================================
// Tensor-core GEMM via mma.sync (HMMA, sm_100-baseline):
//   h = relu([H_dst | hn] @ W^T + b), split-bf16: hi*Whi + hi*Wlo + lo*Whi.
// 256 threads / 8 warps / 128 rows per block; warp w: rows 16w..16w+15, all
// 64 outs. K=128 in 8 k16 steps. x hi/lo in dynamic smem, padded 272B rows.
// ===========================================================================
#define TC_ROWS    128
#define TC_THREADS 256
#define TC_BLOCKS  ((N_DST + TC_ROWS - 1) / TC_ROWS)   // 391
// smem layout (bytes): x_hi[128*272] | x_lo[128*272] | w_hi[64*272] | w_lo[64*272]
#define SM_XHI 0
#define SM_XLO (128 * XPAD)
#define SM_WHI (2 * 128 * XPAD)
#define SM_WLO (2 * 128 * XPAD + 64 * XPAD)
#define TC_SMEM (2 * 128 * XPAD + 2 * 64 * XPAD)       // 104448

__global__ __launch_bounds__(TC_THREADS) void gemm_mma_kernel(
    const float* __restrict__ H_dst,
    const float* __restrict__ hn,
    const float* __restrict__ bias,
    float* __restrict__ out_h)
{
    extern __shared__ char smem[];
    const uint32_t smem_u = smem_to_u32(smem);
    const int tid = threadIdx.x;
    const int wid = tid >> 5;
    const int lane = tid & 31;
    const int rowBase = blockIdx.x * TC_ROWS;

    // --- stage W: linear float4 copy of prep-baked padded images ---
    {
        const float4* shi = (const float4*)g_wbhi;
        const float4* slo = (const float4*)g_wblo;
        float4* dhi = (float4*)(smem + SM_WHI);
        float4* dlo = (float4*)(smem + SM_WLO);
        for (int i = tid; i < 64 * XPAD / 16; i += TC_THREADS) {
            dhi[i] = shi[i];
            dlo[i] = slo[i];
        }
    }

    // --- stage x: thread t -> row t/2, k-half t&1; convert to bf16 hi/lo ---
    // Each half = 64 floats = 16 float4s = 128 bytes bf16 (8 uint4 stores).
    {
        const int r = tid >> 1;             // row within block
        const int h = tid & 1;              // 0: k 0-63 (H_dst), 1: k 64-127 (hn)
        const int row = rowBase + r;
        const bool valid = row < N_DST;
        const float4* src = h ? ((const float4*)hn + (size_t)row * 16)
                              : ((const float4*)H_dst + (size_t)row * 16);
        char* xhi = smem + SM_XHI + r * XPAD + h * 128;
        char* xlo = smem + SM_XLO + r * XPAD + h * 128;
#pragma unroll
        for (int j = 0; j < 8; j++) {       // 8 x 16B bf16 chunks = 64 k-values
            uint32_t hp[4], lp[4];
#pragma unroll
            for (int u = 0; u < 2; u++) {
                float4 q = valid ? src[2 * j + u] : make_float4(0.f, 0.f, 0.f, 0.f);
                uint32_t h0 = bf2(q.x, q.y);
                uint32_t h1 = bf2(q.z, q.w);
                hp[2 * u + 0] = h0;
                hp[2 * u + 1] = h1;
                lp[2 * u + 0] = bf2(q.x - bflo_f(h0), q.y - bfhi_f(h0));
                lp[2 * u + 1] = bf2(q.z - bflo_f(h1), q.w - bfhi_f(h1));
            }
            ((uint4*)xhi)[j] = make_uint4(hp[0], hp[1], hp[2], hp[3]);
            ((uint4*)xlo)[j] = make_uint4(lp[0], lp[1], lp[2], lp[3]);
        }
    }
    __syncthreads();

    // --- mainloop ---
    float acc[8][4];
#pragma unroll
    for (int t = 0; t < 8; t++)
#pragma unroll
        for (int j = 0; j < 4; j++) acc[t][j] = 0.f;

    // A lane address: row = 16*wid + (lane & 15), chunk base = 16*(lane>>4)
    const uint32_t a_off = (uint32_t)(16 * wid + (lane & 15)) * XPAD
                         + 16u * (lane >> 4);
    // B lane address: n = (lane&7) + ((lane>>4)<<3), chunk = ((lane>>3)&1)
    const uint32_t b_row = (uint32_t)((lane & 7) + ((lane >> 4) << 3));
    const uint32_t b_off = b_row * XPAD + 16u * ((lane >> 3) & 1);

#pragma unroll
    for (int s = 0; s < 8; s++) {
        uint32_t ahi[4], alo[4];
        ldsm_x4(ahi, smem_u + SM_XHI + a_off + 32 * s);
        ldsm_x4(alo, smem_u + SM_XLO + a_off + 32 * s);
#pragma unroll
        for (int np = 0; np < 4; np++) {    // n-tile pair: tiles 2np, 2np+1
            uint32_t bhi[4], blo[4];
            uint32_t boff = b_off + (uint32_t)(16 * np) * XPAD + 32 * s;
            ldsm_x4(bhi, smem_u + SM_WHI + boff);
            ldsm_x4(blo, smem_u + SM_WLO + boff);
            mma_bf16(acc[2 * np + 0], ahi, bhi[0], bhi[1]);
            mma_bf16(acc[2 * np + 0], ahi, blo[0], blo[1]);
            mma_bf16(acc[2 * np + 0], alo, bhi[0], bhi[1]);
            mma_bf16(acc[2 * np + 1], ahi, bhi[2], bhi[3]);
            mma_bf16(acc[2 * np + 1], ahi, blo[2], blo[3]);
            mma_bf16(acc[2 * np + 1], alo, bhi[2], bhi[3]);
        }
    }

    // --- epilogue: bias + relu; D frag: rows l/4 and l/4+8, cols (l%4)*2+{0,1} ---
    const int m0 = rowBase + 16 * wid + (lane >> 2);
    const int m1 = m0 + 8;
    const int cb = (lane & 3) * 2;
#pragma unroll
    for (int t = 0; t < 8; t++) {
        int col = 8 * t + cb;
        float2 bv = __ldg((const float2*)&bias[col]);
        if (m0 < N_DST) {
            float2 v;
            v.x = fmaxf(acc[t][0] + bv.x, 0.f);
            v.y = fmaxf(acc[t][1] + bv.y, 0.f);
            *(float2*)&out_h[(size_t)m0 * 64 + col] = v;
        }
        if (m1 < N_DST) {
            float2 v;
            v.x = fmaxf(acc[t][2] + bv.x, 0.f);
            v.y = fmaxf(acc[t][3] + bv.y, 0.f);
            *(float2*)&out_h[(size_t)m1 * 64 + col] = v;
        }
    }
}

// ===========================================================================
extern "C" void kernel_launch(void* const* d_in, const int* in_sizes, int n_in,
                              void* d_out, int out_size) {
    const float* H_src   = (const float*)d_in[0];
    const float* H_dst   = (const float*)d_in[1];
    const float* HBar    = (const float*)d_in[2];
    const int*   src_idx = (const int*)  d_in[3];
    const int*   dst_idx = (const int*)  d_in[4];
    const float* W       = (const float*)d_in[5];
    const float* bias    = (const float*)d_in[6];

    float* out_h  = (float*)d_out;                     // [N_DST, 64]
    float* out_hn = (float*)d_out + N_DST * 64;        // [N_DST, 64]

    prep_kernel<<<QUAD_BLOCKS + W_BLOCKS, 256>>>(dst_idx, W);

    aggregate_kernel<<<(N_DST + AGG_ROWS - 1) / AGG_ROWS, AGG_THREADS>>>(
        H_src, HBar, src_idx, out_hn);

    cudaFuncSetAttribute(gemm_mma_kernel,
                         cudaFuncAttributeMaxDynamicSharedMemorySize, TC_SMEM);
    gemm_mma_kernel<<<TC_BLOCKS, TC_THREADS, TC_SMEM>>>(H_dst, out_hn, bias, out_h);
}